// round 11
// baseline (speedup 1.0000x reference)
#include <cuda_runtime.h>
#include <cstdint>
#include <cmath>

#define BSZ 2
#define PP 512
#define NN 2048
#define DD 768
#define HH 12
#define HD 64
#define ROWS 2560
#define MTOT 5120
#define QKV3 2304

#define NEG_INF __int_as_float(0xff800000)

// Scratch (__device__ globals: allocation-free rule)
__device__ float g_qkv [(size_t)MTOT * QKV3];     // qkv activations f32
__device__ float g_attn[(size_t)MTOT * DD];       // attention output f32
__device__ uint2 g_actp [(size_t)MTOT * (DD/2)];  // packed bf16 hi/lo pairs, row-major (A operand)
__device__ uint2 g_wqkvp[(size_t)QKV3 * (DD/2)];  // qkv_w transposed+packed [n][k-pairs]
__device__ uint2 g_wprojp[(size_t)DD * (DD/2)];   // proj_w transposed+packed
__device__ float g_mbias[BSZ * ROWS];             // -inf where masked, 0 (padded to 2560)

// ---------------------------------------------------------------------------
// helpers
// ---------------------------------------------------------------------------
__device__ __forceinline__ uint32_t pack2bf(float lo, float hi) {
    uint32_t r;
    asm("cvt.rn.bf16x2.f32 %0, %1, %2;" : "=r"(r) : "f"(hi), "f"(lo));
    return r;
}
// split (x0,x1) -> packed hi pair + packed lo pair
__device__ __forceinline__ void splitpack(float x0, float x1, uint32_t& h, uint32_t& l) {
    h = pack2bf(x0, x1);
    const float h0 = __uint_as_float(h << 16);
    const float h1 = __uint_as_float(h & 0xffff0000u);
    l = pack2bf(x0 - h0, x1 - h1);
}
__device__ __forceinline__ void mma16(float4& d, const uint32_t* a, uint32_t b0, uint32_t b1) {
    asm volatile(
        "mma.sync.aligned.m16n8k16.row.col.f32.bf16.bf16.f32 "
        "{%0,%1,%2,%3},{%4,%5,%6,%7},{%8,%9},{%0,%1,%2,%3};"
        : "+f"(d.x), "+f"(d.y), "+f"(d.z), "+f"(d.w)
        : "r"(a[0]), "r"(a[1]), "r"(a[2]), "r"(a[3]), "r"(b0), "r"(b1));
}

// ---------------------------------------------------------------------------
// Mask: detect dtype (bool8 / int32 / float32), build -inf/0 bias padded to 2560
// ---------------------------------------------------------------------------
__global__ void mask_convert(const uint32_t* __restrict__ mw)
{
    __shared__ int is_bool;
    const int tid = threadIdx.x;
    if (tid == 0) is_bool = 0;
    __syncthreads();
    if (tid < 256) {
        uint32_t w = mw[tid];
        if (w > 1u && w != 0x3F800000u) atomicOr(&is_bool, 1);
    }
    __syncthreads();
    const int i = blockIdx.x * 1024 + tid;
    const int b = i / ROWS, p = i % ROWS;
    float v = 0.0f;
    if (p < PP) {
        const int mi = b * PP + p;
        bool m = is_bool ? (((const uint8_t*)mw)[mi] != 0) : (mw[mi] != 0u);
        v = m ? NEG_INF : 0.0f;
    }
    g_mbias[i] = v;
}

// ---------------------------------------------------------------------------
// Pack activations (virtual concat [xq; xs]) -> g_actp (row-major bf16 hi/lo pairs)
// ---------------------------------------------------------------------------
__global__ void pack_act(const float* __restrict__ xs, const float* __restrict__ xq)
{
    const int i = blockIdx.x * 256 + threadIdx.x;   // over MTOT*192 uint4 entries
    const int row = i / 192, q = i % 192;
    const int b = row / ROWS, r = row % ROWS;
    const float* src = (r < NN) ? xq + ((size_t)b * NN + r) * DD
                                : xs + ((size_t)b * PP + (r - NN)) * DD;
    float4 v = *(const float4*)(src + q * 4);
    uint4 o;
    splitpack(v.x, v.y, o.x, o.y);
    splitpack(v.z, v.w, o.z, o.w);
    ((uint4*)g_actp)[(size_t)row * 192 + q] = o;
}

__global__ void pack_attn()
{
    const int i = blockIdx.x * 256 + threadIdx.x;
    float4 v = *(const float4*)(g_attn + (size_t)i * 4);
    uint4 o;
    splitpack(v.x, v.y, o.x, o.y);
    splitpack(v.z, v.w, o.z, o.w);
    ((uint4*)g_actp)[i] = o;
}

// ---------------------------------------------------------------------------
// Transpose + pack weights: src row-major [768][NB] -> dst [NB][384] uint2
// (k-major pairs per output column), 32x32 smem tiles.
// ---------------------------------------------------------------------------
__global__ void tpack(const float* __restrict__ src, uint2* __restrict__ dst, int NB)
{
    __shared__ float t[32][33];
    const int tid = threadIdx.x;
    const int n0 = blockIdx.x * 32, k0 = blockIdx.y * 32;
#pragma unroll
    for (int s = 0; s < 4; s++) {
        const int r = (tid >> 5) + s * 8, c = tid & 31;
        t[r][c] = src[(size_t)(k0 + r) * NB + n0 + c];
    }
    __syncthreads();
#pragma unroll
    for (int s = 0; s < 2; s++) {
        const int i = (tid >> 4) + s * 16, j = tid & 15;
        uint32_t h, l;
        splitpack(t[2 * j][i], t[2 * j + 1][i], h, l);
        dst[(size_t)(n0 + i) * 384 + k0 / 2 + j] = make_uint2(h, l);
    }
}

// ---------------------------------------------------------------------------
// 3-term bf16 GEMM: C[M x NB] = A[M x 768] @ B[768 x NB] + bias
// A = g_actp (row-major pairs), B = transposed/packed weights.
// 128x128 tile, BK=32, 8 warps (4x2), warp tile 32x64, m16n8k16.
// smem: uint2 arrays, stride 18 (uint4-aligned staging writes).
// EPI 0 -> g_qkv; EPI 1 -> tuple-scatter to output.
// ---------------------------------------------------------------------------
#define GST 18
#define GEMM_SMEM (2 * 128 * GST * 8)

template <int EPI>
__global__ __launch_bounds__(256) void gemm_bf(
    const uint2* __restrict__ Bg, const float* __restrict__ bias, float* __restrict__ Cout)
{
    constexpr int NB = (EPI == 0) ? QKV3 : DD;
    extern __shared__ uint2 sm2[];
    uint2* As2 = sm2;                 // [128][GST]
    uint2* Bs2 = sm2 + 128 * GST;     // [128][GST]

    const int tid = threadIdx.x;
    const int bx = blockIdx.x, by = blockIdx.y;
    const int wid = tid >> 5, lane = tid & 31;
    const int wm = wid >> 1, wn = wid & 1;
    const int lg = lane >> 2, lt = lane & 3;
    const int row0 = by * 128, col0 = bx * 128;

    float4 acc[2][8];
#pragma unroll
    for (int mi = 0; mi < 2; mi++)
#pragma unroll
        for (int ni = 0; ni < 8; ni++) acc[mi][ni] = make_float4(0.f, 0.f, 0.f, 0.f);

    const uint4* Ag4 = (const uint4*)g_actp;
    const uint4* Bg4 = (const uint4*)Bg;
    uint4* As4 = (uint4*)As2;
    uint4* Bs4 = (uint4*)Bs2;

    for (int k0 = 0; k0 < DD; k0 += 32) {
        __syncthreads();
        const int kt = k0 / 4;                     // uint4 offset within row
#pragma unroll
        for (int i = 0; i < 4; i++) {
            const int id = tid + i * 256;          // 1024 entries
            const int r = id >> 3, q = id & 7;
            As4[r * (GST / 2) + q] = Ag4[(size_t)(row0 + r) * 192 + kt + q];
            Bs4[r * (GST / 2) + q] = Bg4[(size_t)(col0 + r) * 192 + kt + q];
        }
        __syncthreads();

#pragma unroll
        for (int ks = 0; ks < 2; ks++) {
            const int kb = ks * 8 + lt;
            uint32_t ah[2][4], al[2][4];
#pragma unroll
            for (int mi = 0; mi < 2; mi++) {
                const int rb = wm * 32 + mi * 16;
                const uint2 A0 = As2[(rb + lg) * GST + kb];
                const uint2 A1 = As2[(rb + 8 + lg) * GST + kb];
                const uint2 A2 = As2[(rb + lg) * GST + kb + 4];
                const uint2 A3 = As2[(rb + 8 + lg) * GST + kb + 4];
                ah[mi][0] = A0.x; ah[mi][1] = A1.x; ah[mi][2] = A2.x; ah[mi][3] = A3.x;
                al[mi][0] = A0.y; al[mi][1] = A1.y; al[mi][2] = A2.y; al[mi][3] = A3.y;
            }
#pragma unroll
            for (int ni = 0; ni < 8; ni++) {
                const int col = wn * 64 + ni * 8 + lg;
                const uint2 B0 = Bs2[col * GST + kb];
                const uint2 B1 = Bs2[col * GST + kb + 4];
#pragma unroll
                for (int mi = 0; mi < 2; mi++) {
                    mma16(acc[mi][ni], ah[mi], B0.x, B1.x);   // hh
                    mma16(acc[mi][ni], ah[mi], B0.y, B1.y);   // hl
                    mma16(acc[mi][ni], al[mi], B0.x, B1.x);   // lh
                }
            }
        }
    }

    // Epilogue
#pragma unroll
    for (int mi = 0; mi < 2; mi++) {
        const int r0 = row0 + wm * 32 + mi * 16 + lg;
#pragma unroll
        for (int ni = 0; ni < 8; ni++) {
            const int col = col0 + wn * 64 + ni * 8 + lt * 2;
            const float b0 = __ldg(&bias[col]), b1 = __ldg(&bias[col + 1]);
            float2 v0 = {acc[mi][ni].x + b0, acc[mi][ni].y + b1};
            float2 v1 = {acc[mi][ni].z + b0, acc[mi][ni].w + b1};
            if (EPI == 0) {
                *(float2*)(g_qkv + (size_t)r0 * NB + col) = v0;
                *(float2*)(g_qkv + (size_t)(r0 + 8) * NB + col) = v1;
            } else {
#pragma unroll
                for (int rr = 0; rr < 2; rr++) {
                    const int g = r0 + rr * 8;
                    const int b = g / ROWS, r = g % ROWS;
                    float* dst = (r < PP)
                        ? Cout + ((size_t)b * PP + r) * DD
                        : Cout + (size_t)BSZ * PP * DD + ((size_t)b * NN + (r - PP)) * DD;
                    *(float2*)(dst + col) = rr ? v1 : v0;
                }
            }
        }
    }
}

// ---------------------------------------------------------------------------
// bf16 3-term flash attention. BQ=128 (8 warps x 16 rows), BKV=64, d=64.
// Q fragments (hi+lo) in registers for the whole KV loop.
// K in smem k-major pairs [kv][d-pair]; V transposed [d][kv-pair].
// P C-layout -> bf16 A-frag via direct pair packing (no shuffles).
// ---------------------------------------------------------------------------
#define QST 34                        // Q/K smem stride (uint2)
#define VSTR 33                       // V smem stride (uint2)
#define ATTN_SMEM (128 * QST * 8 + 512)

__global__ __launch_bounds__(256) void attn_bf(int q_start, int Lk, int self_mode)
{
    extern __shared__ uint2 sm2[];
    uint2* Qs2 = sm2;                            // [128][QST] (staging, then free)
    uint2* Ks2 = sm2;                            // [64][QST]
    uint2* Vs2 = sm2 + 64 * QST;                 // [64][VSTR]
    float* msk = (float*)(sm2 + 64 * QST + 64 * VSTR);   // [64]

    const int tid = threadIdx.x, wid = tid >> 5, lane = tid & 31;
    const int lg = lane >> 2, lt = lane & 3;
    const int h = blockIdx.y, b = blockIdx.z;
    const int q0 = blockIdx.x * 128;
    const size_t rowbase = (size_t)b * ROWS;

    // ---- Stage Q (split+pack) and pull fragments to registers ----
    const float* qg = g_qkv + (rowbase + q_start + q0) * QKV3 + h * HD;
    uint4* Qs4 = (uint4*)Qs2;
#pragma unroll
    for (int i = 0; i < 8; i++) {
        const int id = tid + i * 256;            // 2048 = 128 rows x 16 float4
        const int r = id >> 4, fq = id & 15;
        float4 v = *(const float4*)(qg + (size_t)r * QKV3 + fq * 4);
        uint4 o;
        splitpack(v.x, v.y, o.x, o.y);
        splitpack(v.z, v.w, o.z, o.w);
        Qs4[r * (QST / 2) + fq] = o;
    }
    __syncthreads();
    uint32_t qfh[4][4], qfl[4][4];
    {
        const int qrow = wid * 16 + lg;
#pragma unroll
        for (int kf = 0; kf < 4; kf++) {
            const int kb = kf * 8 + lt;
            const uint2 Q0 = Qs2[qrow * QST + kb];
            const uint2 Q1 = Qs2[(qrow + 8) * QST + kb];
            const uint2 Q2 = Qs2[qrow * QST + kb + 4];
            const uint2 Q3 = Qs2[(qrow + 8) * QST + kb + 4];
            qfh[kf][0] = Q0.x; qfh[kf][1] = Q1.x; qfh[kf][2] = Q2.x; qfh[kf][3] = Q3.x;
            qfl[kf][0] = Q0.y; qfl[kf][1] = Q1.y; qfl[kf][2] = Q2.y; qfl[kf][3] = Q3.y;
        }
    }

    float4 oacc[8];
#pragma unroll
    for (int d = 0; d < 8; d++) oacc[d] = make_float4(0.f, 0.f, 0.f, 0.f);
    float m0 = NEG_INF, m1 = NEG_INF, l0 = 0.f, l1 = 0.f;

    for (int kv0 = 0; kv0 < Lk; kv0 += 64) {
        __syncthreads();
        const float* kg = g_qkv + (rowbase + kv0) * QKV3 + DD + h * HD;
        const float* vg = kg + DD;
        uint4* Ks4 = (uint4*)Ks2;
#pragma unroll
        for (int i = 0; i < 4; i++) {
            const int id = tid + i * 256;        // 1024 = 64 rows x 16 float4
            const int r = id >> 4, fq = id & 15;
            float4 v = *(const float4*)(kg + (size_t)r * QKV3 + fq * 4);
            uint4 o;
            splitpack(v.x, v.y, o.x, o.y);
            splitpack(v.z, v.w, o.z, o.w);
            Ks4[r * (QST / 2) + fq] = o;
        }
        // V transposed: Vs2[d][kvp] = pair over kv
#pragma unroll
        for (int e = 0; e < 8; e++) {
            const int idx = tid + e * 256;       // 2048 = 64 d x 32 kv-pairs
            const int d = idx & 63, kvp = idx >> 6;
            const float f0 = vg[(size_t)(2 * kvp) * QKV3 + d];
            const float f1 = vg[(size_t)(2 * kvp + 1) * QKV3 + d];
            uint32_t hh, ll;
            splitpack(f0, f1, hh, ll);
            Vs2[d * VSTR + kvp] = make_uint2(hh, ll);
        }
        if (tid < 64) msk[tid] = g_mbias[b * ROWS + kv0 + tid];
        __syncthreads();

        // ---- S = Q @ K^T (3-term bf16) ----
        float4 sacc[8];
#pragma unroll
        for (int ni = 0; ni < 8; ni++) sacc[ni] = make_float4(0.f, 0.f, 0.f, 0.f);
#pragma unroll
        for (int kf = 0; kf < 4; kf++) {
            const int kb = kf * 8 + lt;
#pragma unroll
            for (int ni = 0; ni < 8; ni++) {
                const int n = ni * 8 + lg;
                const uint2 K0 = Ks2[n * QST + kb];
                const uint2 K1 = Ks2[n * QST + kb + 4];
                mma16(sacc[ni], qfh[kf], K0.x, K1.x);
                mma16(sacc[ni], qfh[kf], K0.y, K1.y);
                mma16(sacc[ni], qfl[kf], K0.x, K1.x);
            }
        }

        // ---- scale + mask bias, online softmax ----
        float rmax0 = NEG_INF, rmax1 = NEG_INF;
#pragma unroll
        for (int ni = 0; ni < 8; ni++) {
            const float mb0 = msk[ni * 8 + lt * 2];
            const float mb1 = msk[ni * 8 + lt * 2 + 1];
            sacc[ni].x = sacc[ni].x * 0.125f + mb0;
            sacc[ni].y = sacc[ni].y * 0.125f + mb1;
            sacc[ni].z = sacc[ni].z * 0.125f + mb0;
            sacc[ni].w = sacc[ni].w * 0.125f + mb1;
            rmax0 = fmaxf(rmax0, fmaxf(sacc[ni].x, sacc[ni].y));
            rmax1 = fmaxf(rmax1, fmaxf(sacc[ni].z, sacc[ni].w));
        }
        rmax0 = fmaxf(rmax0, __shfl_xor_sync(0xffffffffu, rmax0, 1));
        rmax0 = fmaxf(rmax0, __shfl_xor_sync(0xffffffffu, rmax0, 2));
        rmax1 = fmaxf(rmax1, __shfl_xor_sync(0xffffffffu, rmax1, 1));
        rmax1 = fmaxf(rmax1, __shfl_xor_sync(0xffffffffu, rmax1, 2));

        const float nm0 = fmaxf(m0, rmax0), nm1 = fmaxf(m1, rmax1);
        const float s0 = (nm0 == NEG_INF) ? 0.f : nm0;
        const float s1 = (nm1 == NEG_INF) ? 0.f : nm1;
        const float f0 = __expf(m0 - s0), f1 = __expf(m1 - s1);
        m0 = nm0; m1 = nm1;

        float rs0 = 0.f, rs1 = 0.f;
#pragma unroll
        for (int ni = 0; ni < 8; ni++) {
            sacc[ni].x = __expf(sacc[ni].x - s0);
            sacc[ni].y = __expf(sacc[ni].y - s0);
            sacc[ni].z = __expf(sacc[ni].z - s1);
            sacc[ni].w = __expf(sacc[ni].w - s1);
            rs0 += sacc[ni].x + sacc[ni].y;
            rs1 += sacc[ni].z + sacc[ni].w;
        }
        rs0 += __shfl_xor_sync(0xffffffffu, rs0, 1);
        rs0 += __shfl_xor_sync(0xffffffffu, rs0, 2);
        rs1 += __shfl_xor_sync(0xffffffffu, rs1, 1);
        rs1 += __shfl_xor_sync(0xffffffffu, rs1, 2);
        l0 = l0 * f0 + rs0;
        l1 = l1 * f1 + rs1;
#pragma unroll
        for (int d = 0; d < 8; d++) {
            oacc[d].x *= f0; oacc[d].y *= f0;
            oacc[d].z *= f1; oacc[d].w *= f1;
        }

        // ---- O += P @ V : C-layout pairs pack directly into A-frags ----
#pragma unroll
        for (int g = 0; g < 4; g++) {
            uint32_t pah[4], pal[4];
            splitpack(sacc[2 * g].x,     sacc[2 * g].y,     pah[0], pal[0]);
            splitpack(sacc[2 * g].z,     sacc[2 * g].w,     pah[1], pal[1]);
            splitpack(sacc[2 * g + 1].x, sacc[2 * g + 1].y, pah[2], pal[2]);
            splitpack(sacc[2 * g + 1].z, sacc[2 * g + 1].w, pah[3], pal[3]);
#pragma unroll
            for (int dc = 0; dc < 8; dc++) {
                const int col = dc * 8 + lg;
                const uint2 V0 = Vs2[col * VSTR + g * 8 + lt];
                const uint2 V1 = Vs2[col * VSTR + g * 8 + 4 + lt];
                mma16(oacc[dc], pah, V0.x, V1.x);
                mma16(oacc[dc], pah, V0.y, V1.y);
                mma16(oacc[dc], pal, V0.x, V1.x);
            }
        }
    }

    // ---- finalize ----
    const float inv0 = 1.f / l0, inv1 = 1.f / l1;
    if (!self_mode) {
        const int r0 = q_start + q0 + wid * 16 + lg;
#pragma unroll
        for (int d = 0; d < 8; d++) {
            const int col = h * HD + d * 8 + lt * 2;
            float2 a = {oacc[d].x * inv0, oacc[d].y * inv0};
            float2 c = {oacc[d].z * inv1, oacc[d].w * inv1};
            *(float2*)(g_attn + (rowbase + r0) * DD + col) = a;
            *(float2*)(g_attn + (rowbase + r0 + 8) * DD + col) = c;
        }
    } else {
        const int p0 = q0 + wid * 16 + lg, p1 = p0 + 8;
#pragma unroll
        for (int d = 0; d < 8; d++) {
            const int k = d * 8 + lt * 2;
#pragma unroll
            for (int e = 0; e < 4; e++) {
                const int kk = k + (e & 1);
                const int pp = (e < 2) ? p0 : p1;
                const float val = ((e == 0) ? oacc[d].x * inv0 :
                                   (e == 1) ? oacc[d].y * inv0 :
                                   (e == 2) ? oacc[d].z * inv1 : oacc[d].w * inv1);
                const int f = (h * HD + kk) * PP + pp;
                g_attn[(rowbase + f / DD) * DD + (f % DD)] = val;
            }
        }
    }
}

// ---------------------------------------------------------------------------
extern "C" void kernel_launch(void* const* d_in, const int* in_sizes, int n_in,
                              void* d_out, int out_size)
{
    const float*    xs     = (const float*)d_in[0];
    const float*    xq     = (const float*)d_in[1];
    const uint32_t* mask   = (const uint32_t*)d_in[2];
    const float*    qkv_w  = (const float*)d_in[3];
    const float*    qkv_b  = (const float*)d_in[4];
    const float*    proj_w = (const float*)d_in[5];
    const float*    proj_b = (const float*)d_in[6];
    float*          out    = (float*)d_out;
    (void)in_sizes; (void)n_in; (void)out_size;

    cudaFuncSetAttribute(gemm_bf<0>, cudaFuncAttributeMaxDynamicSharedMemorySize, GEMM_SMEM);
    cudaFuncSetAttribute(gemm_bf<1>, cudaFuncAttributeMaxDynamicSharedMemorySize, GEMM_SMEM);
    cudaFuncSetAttribute(attn_bf, cudaFuncAttributeMaxDynamicSharedMemorySize, ATTN_SMEM);

    // 0) mask + operand packing
    mask_convert<<<5, 1024>>>(mask);
    pack_act<<<(MTOT * 192) / 256, 256>>>(xs, xq);
    tpack<<<dim3(QKV3 / 32, DD / 32), 256>>>(qkv_w, g_wqkvp, QKV3);
    tpack<<<dim3(DD / 32, DD / 32), 256>>>(proj_w, g_wprojp, DD);

    // 1) QKV projection (3-term bf16)
    gemm_bf<0><<<dim3(QKV3 / 128, MTOT / 128), 256, GEMM_SMEM>>>(g_wqkvp, qkv_b, nullptr);

    // 2) cross attention: Q rows [P, P+N), KV rows [0, 2560)
    attn_bf<<<dim3(NN / 128, HH, BSZ), 256, ATTN_SMEM>>>(PP, ROWS, 0);

    // 3) self attention: Q rows [0, P), KV rows [0, P), scrambled scatter
    attn_bf<<<dim3(PP / 128, HH, BSZ), 256, ATTN_SMEM>>>(0, PP, 1);

    // 4) pack attention output, then proj (3-term bf16) + tuple scatter
    pack_attn<<<(MTOT * 192) / 256, 256>>>();
    gemm_bf<1><<<dim3(DD / 128, MTOT / 128), 256, GEMM_SMEM>>>(g_wprojp, proj_b, out);
}

// round 12
// speedup vs baseline: 1.0040x; 1.0040x over previous
#include <cuda_runtime.h>
#include <cstdint>
#include <cmath>

#define BSZ 2
#define PP 512
#define NN 2048
#define DD 768
#define HH 12
#define HD 64
#define ROWS 2560
#define MTOT 5120
#define QKV3 2304

#define NEG_INF __int_as_float(0xff800000)

// Scratch (__device__ globals: allocation-free rule)
__device__ float g_qkv [(size_t)MTOT * QKV3];     // qkv activations f32
__device__ float g_attn[(size_t)MTOT * DD];       // attention output f32
__device__ uint2 g_actp [(size_t)MTOT * (DD/2)];  // packed bf16 hi/lo pairs, row-major (A operand)
__device__ uint2 g_wqkvp[(size_t)QKV3 * (DD/2)];  // qkv_w transposed+packed [n][k-pairs]
__device__ uint2 g_wprojp[(size_t)DD * (DD/2)];   // proj_w transposed+packed
__device__ float g_mbias[BSZ * ROWS];             // -inf where masked, 0 (padded to 2560)

// ---------------------------------------------------------------------------
// helpers
// ---------------------------------------------------------------------------
__device__ __forceinline__ uint32_t pack2bf(float lo, float hi) {
    uint32_t r;
    asm("cvt.rn.bf16x2.f32 %0, %1, %2;" : "=r"(r) : "f"(hi), "f"(lo));
    return r;
}
// split (x0,x1) -> packed hi pair + packed lo pair
__device__ __forceinline__ void splitpack(float x0, float x1, uint32_t& h, uint32_t& l) {
    h = pack2bf(x0, x1);
    const float h0 = __uint_as_float(h << 16);
    const float h1 = __uint_as_float(h & 0xffff0000u);
    l = pack2bf(x0 - h0, x1 - h1);
}
__device__ __forceinline__ void mma16(float4& d, const uint32_t* a, uint32_t b0, uint32_t b1) {
    asm volatile(
        "mma.sync.aligned.m16n8k16.row.col.f32.bf16.bf16.f32 "
        "{%0,%1,%2,%3},{%4,%5,%6,%7},{%8,%9},{%0,%1,%2,%3};"
        : "+f"(d.x), "+f"(d.y), "+f"(d.z), "+f"(d.w)
        : "r"(a[0]), "r"(a[1]), "r"(a[2]), "r"(a[3]), "r"(b0), "r"(b1));
}

// ---------------------------------------------------------------------------
// Mask: detect dtype (bool8 / int32 / float32), build -inf/0 bias padded to 2560
// ---------------------------------------------------------------------------
__global__ void mask_convert(const uint32_t* __restrict__ mw)
{
    __shared__ int is_bool;
    const int tid = threadIdx.x;
    if (tid == 0) is_bool = 0;
    __syncthreads();
    if (tid < 256) {
        uint32_t w = mw[tid];
        if (w > 1u && w != 0x3F800000u) atomicOr(&is_bool, 1);
    }
    __syncthreads();
    const int i = blockIdx.x * 1024 + tid;
    const int b = i / ROWS, p = i % ROWS;
    float v = 0.0f;
    if (p < PP) {
        const int mi = b * PP + p;
        bool m = is_bool ? (((const uint8_t*)mw)[mi] != 0) : (mw[mi] != 0u);
        v = m ? NEG_INF : 0.0f;
    }
    g_mbias[i] = v;
}

// ---------------------------------------------------------------------------
// Pack activations (virtual concat [xq; xs]) -> g_actp (row-major bf16 hi/lo pairs)
// ---------------------------------------------------------------------------
__global__ void pack_act(const float* __restrict__ xs, const float* __restrict__ xq)
{
    const int i = blockIdx.x * 256 + threadIdx.x;   // over MTOT*192 uint4 entries
    const int row = i / 192, q = i % 192;
    const int b = row / ROWS, r = row % ROWS;
    const float* src = (r < NN) ? xq + ((size_t)b * NN + r) * DD
                                : xs + ((size_t)b * PP + (r - NN)) * DD;
    float4 v = *(const float4*)(src + q * 4);
    uint4 o;
    splitpack(v.x, v.y, o.x, o.y);
    splitpack(v.z, v.w, o.z, o.w);
    ((uint4*)g_actp)[(size_t)row * 192 + q] = o;
}

__global__ void pack_attn()
{
    const int i = blockIdx.x * 256 + threadIdx.x;
    float4 v = *(const float4*)(g_attn + (size_t)i * 4);
    uint4 o;
    splitpack(v.x, v.y, o.x, o.y);
    splitpack(v.z, v.w, o.z, o.w);
    ((uint4*)g_actp)[i] = o;
}

// ---------------------------------------------------------------------------
// Transpose + pack weights: src row-major [768][NB] -> dst [NB][384] uint2
// (k-major pairs per output column), 32x32 smem tiles.
// ---------------------------------------------------------------------------
__global__ void tpack(const float* __restrict__ src, uint2* __restrict__ dst, int NB)
{
    __shared__ float t[32][33];
    const int tid = threadIdx.x;
    const int n0 = blockIdx.x * 32, k0 = blockIdx.y * 32;
#pragma unroll
    for (int s = 0; s < 4; s++) {
        const int r = (tid >> 5) + s * 8, c = tid & 31;
        t[r][c] = src[(size_t)(k0 + r) * NB + n0 + c];
    }
    __syncthreads();
#pragma unroll
    for (int s = 0; s < 2; s++) {
        const int i = (tid >> 4) + s * 16, j = tid & 15;
        uint32_t h, l;
        splitpack(t[2 * j][i], t[2 * j + 1][i], h, l);
        dst[(size_t)(n0 + i) * 384 + k0 / 2 + j] = make_uint2(h, l);
    }
}

// ---------------------------------------------------------------------------
// 3-term bf16 GEMM: C[M x NB] = A[M x 768] @ B[768 x NB] + bias
// A = g_actp (row-major pairs), B = transposed/packed weights.
// 128x128 tile, BK=32, 8 warps (4x2), warp tile 32x64, m16n8k16.
// smem: uint2 arrays, stride 18 (uint4-aligned staging writes).
// EPI 0 -> g_qkv; EPI 1 -> tuple-scatter to output.
// ---------------------------------------------------------------------------
#define GST 18
#define GEMM_SMEM (2 * 128 * GST * 8)

template <int EPI>
__global__ __launch_bounds__(256) void gemm_bf(
    const uint2* __restrict__ Bg, const float* __restrict__ bias, float* __restrict__ Cout)
{
    constexpr int NB = (EPI == 0) ? QKV3 : DD;
    extern __shared__ uint2 sm2[];
    uint2* As2 = sm2;                 // [128][GST]
    uint2* Bs2 = sm2 + 128 * GST;     // [128][GST]

    const int tid = threadIdx.x;
    const int bx = blockIdx.x, by = blockIdx.y;
    const int wid = tid >> 5, lane = tid & 31;
    const int wm = wid >> 1, wn = wid & 1;
    const int lg = lane >> 2, lt = lane & 3;
    const int row0 = by * 128, col0 = bx * 128;

    float4 acc[2][8];
#pragma unroll
    for (int mi = 0; mi < 2; mi++)
#pragma unroll
        for (int ni = 0; ni < 8; ni++) acc[mi][ni] = make_float4(0.f, 0.f, 0.f, 0.f);

    const uint4* Ag4 = (const uint4*)g_actp;
    const uint4* Bg4 = (const uint4*)Bg;
    uint4* As4 = (uint4*)As2;
    uint4* Bs4 = (uint4*)Bs2;

    for (int k0 = 0; k0 < DD; k0 += 32) {
        __syncthreads();
        const int kt = k0 / 4;                     // uint4 offset within row
#pragma unroll
        for (int i = 0; i < 4; i++) {
            const int id = tid + i * 256;          // 1024 entries
            const int r = id >> 3, q = id & 7;
            As4[r * (GST / 2) + q] = Ag4[(size_t)(row0 + r) * 192 + kt + q];
            Bs4[r * (GST / 2) + q] = Bg4[(size_t)(col0 + r) * 192 + kt + q];
        }
        __syncthreads();

#pragma unroll
        for (int ks = 0; ks < 2; ks++) {
            const int kb = ks * 8 + lt;
            uint32_t ah[2][4], al[2][4];
#pragma unroll
            for (int mi = 0; mi < 2; mi++) {
                const int rb = wm * 32 + mi * 16;
                const uint2 A0 = As2[(rb + lg) * GST + kb];
                const uint2 A1 = As2[(rb + 8 + lg) * GST + kb];
                const uint2 A2 = As2[(rb + lg) * GST + kb + 4];
                const uint2 A3 = As2[(rb + 8 + lg) * GST + kb + 4];
                ah[mi][0] = A0.x; ah[mi][1] = A1.x; ah[mi][2] = A2.x; ah[mi][3] = A3.x;
                al[mi][0] = A0.y; al[mi][1] = A1.y; al[mi][2] = A2.y; al[mi][3] = A3.y;
            }
#pragma unroll
            for (int ni = 0; ni < 8; ni++) {
                const int col = wn * 64 + ni * 8 + lg;
                const uint2 B0 = Bs2[col * GST + kb];
                const uint2 B1 = Bs2[col * GST + kb + 4];
#pragma unroll
                for (int mi = 0; mi < 2; mi++) {
                    mma16(acc[mi][ni], ah[mi], B0.x, B1.x);   // hh
                    mma16(acc[mi][ni], ah[mi], B0.y, B1.y);   // hl
                    mma16(acc[mi][ni], al[mi], B0.x, B1.x);   // lh
                }
            }
        }
    }

    // Epilogue
#pragma unroll
    for (int mi = 0; mi < 2; mi++) {
        const int r0 = row0 + wm * 32 + mi * 16 + lg;
#pragma unroll
        for (int ni = 0; ni < 8; ni++) {
            const int col = col0 + wn * 64 + ni * 8 + lt * 2;
            const float b0 = __ldg(&bias[col]), b1 = __ldg(&bias[col + 1]);
            float2 v0 = {acc[mi][ni].x + b0, acc[mi][ni].y + b1};
            float2 v1 = {acc[mi][ni].z + b0, acc[mi][ni].w + b1};
            if (EPI == 0) {
                *(float2*)(g_qkv + (size_t)r0 * NB + col) = v0;
                *(float2*)(g_qkv + (size_t)(r0 + 8) * NB + col) = v1;
            } else {
#pragma unroll
                for (int rr = 0; rr < 2; rr++) {
                    const int g = r0 + rr * 8;
                    const int b = g / ROWS, r = g % ROWS;
                    float* dst = (r < PP)
                        ? Cout + ((size_t)b * PP + r) * DD
                        : Cout + (size_t)BSZ * PP * DD + ((size_t)b * NN + (r - PP)) * DD;
                    *(float2*)(dst + col) = rr ? v1 : v0;
                }
            }
        }
    }
}

// ---------------------------------------------------------------------------
// bf16 3-term flash attention. BQ=128 (8 warps x 16 rows), BKV=64, d=64.
// Q fragments (hi+lo) in registers for the whole KV loop.
// K in smem k-major pairs [kv][d-pair]; V transposed [d][kv-pair].
// P C-layout -> bf16 A-frag via direct pair packing (no shuffles).
// ---------------------------------------------------------------------------
#define QST 34                        // Q/K smem stride (uint2)
#define VSTR 33                       // V smem stride (uint2)
#define ATTN_SMEM (128 * QST * 8 + 512)

__global__ __launch_bounds__(256) void attn_bf(int q_start, int Lk, int self_mode)
{
    extern __shared__ uint2 sm2[];
    uint2* Qs2 = sm2;                            // [128][QST] (staging, then free)
    uint2* Ks2 = sm2;                            // [64][QST]
    uint2* Vs2 = sm2 + 64 * QST;                 // [64][VSTR]
    float* msk = (float*)(sm2 + 64 * QST + 64 * VSTR);   // [64]

    const int tid = threadIdx.x, wid = tid >> 5, lane = tid & 31;
    const int lg = lane >> 2, lt = lane & 3;
    const int h = blockIdx.y, b = blockIdx.z;
    const int q0 = blockIdx.x * 128;
    const size_t rowbase = (size_t)b * ROWS;

    // ---- Stage Q (split+pack) and pull fragments to registers ----
    const float* qg = g_qkv + (rowbase + q_start + q0) * QKV3 + h * HD;
    uint4* Qs4 = (uint4*)Qs2;
#pragma unroll
    for (int i = 0; i < 8; i++) {
        const int id = tid + i * 256;            // 2048 = 128 rows x 16 float4
        const int r = id >> 4, fq = id & 15;
        float4 v = *(const float4*)(qg + (size_t)r * QKV3 + fq * 4);
        uint4 o;
        splitpack(v.x, v.y, o.x, o.y);
        splitpack(v.z, v.w, o.z, o.w);
        Qs4[r * (QST / 2) + fq] = o;
    }
    __syncthreads();
    uint32_t qfh[4][4], qfl[4][4];
    {
        const int qrow = wid * 16 + lg;
#pragma unroll
        for (int kf = 0; kf < 4; kf++) {
            const int kb = kf * 8 + lt;
            const uint2 Q0 = Qs2[qrow * QST + kb];
            const uint2 Q1 = Qs2[(qrow + 8) * QST + kb];
            const uint2 Q2 = Qs2[qrow * QST + kb + 4];
            const uint2 Q3 = Qs2[(qrow + 8) * QST + kb + 4];
            qfh[kf][0] = Q0.x; qfh[kf][1] = Q1.x; qfh[kf][2] = Q2.x; qfh[kf][3] = Q3.x;
            qfl[kf][0] = Q0.y; qfl[kf][1] = Q1.y; qfl[kf][2] = Q2.y; qfl[kf][3] = Q3.y;
        }
    }

    float4 oacc[8];
#pragma unroll
    for (int d = 0; d < 8; d++) oacc[d] = make_float4(0.f, 0.f, 0.f, 0.f);
    float m0 = NEG_INF, m1 = NEG_INF, l0 = 0.f, l1 = 0.f;

    for (int kv0 = 0; kv0 < Lk; kv0 += 64) {
        __syncthreads();
        const float* kg = g_qkv + (rowbase + kv0) * QKV3 + DD + h * HD;
        const float* vg = kg + DD;
        uint4* Ks4 = (uint4*)Ks2;
#pragma unroll
        for (int i = 0; i < 4; i++) {
            const int id = tid + i * 256;        // 1024 = 64 rows x 16 float4
            const int r = id >> 4, fq = id & 15;
            float4 v = *(const float4*)(kg + (size_t)r * QKV3 + fq * 4);
            uint4 o;
            splitpack(v.x, v.y, o.x, o.y);
            splitpack(v.z, v.w, o.z, o.w);
            Ks4[r * (QST / 2) + fq] = o;
        }
        // V transposed: Vs2[d][kvp] = pair over kv
#pragma unroll
        for (int e = 0; e < 8; e++) {
            const int idx = tid + e * 256;       // 2048 = 64 d x 32 kv-pairs
            const int d = idx & 63, kvp = idx >> 6;
            const float f0 = vg[(size_t)(2 * kvp) * QKV3 + d];
            const float f1 = vg[(size_t)(2 * kvp + 1) * QKV3 + d];
            uint32_t hh, ll;
            splitpack(f0, f1, hh, ll);
            Vs2[d * VSTR + kvp] = make_uint2(hh, ll);
        }
        if (tid < 64) msk[tid] = g_mbias[b * ROWS + kv0 + tid];
        __syncthreads();

        // ---- S = Q @ K^T (3-term bf16) ----
        float4 sacc[8];
#pragma unroll
        for (int ni = 0; ni < 8; ni++) sacc[ni] = make_float4(0.f, 0.f, 0.f, 0.f);
#pragma unroll
        for (int kf = 0; kf < 4; kf++) {
            const int kb = kf * 8 + lt;
#pragma unroll
            for (int ni = 0; ni < 8; ni++) {
                const int n = ni * 8 + lg;
                const uint2 K0 = Ks2[n * QST + kb];
                const uint2 K1 = Ks2[n * QST + kb + 4];
                mma16(sacc[ni], qfh[kf], K0.x, K1.x);
                mma16(sacc[ni], qfh[kf], K0.y, K1.y);
                mma16(sacc[ni], qfl[kf], K0.x, K1.x);
            }
        }

        // ---- scale + mask bias, online softmax ----
        float rmax0 = NEG_INF, rmax1 = NEG_INF;
#pragma unroll
        for (int ni = 0; ni < 8; ni++) {
            const float mb0 = msk[ni * 8 + lt * 2];
            const float mb1 = msk[ni * 8 + lt * 2 + 1];
            sacc[ni].x = sacc[ni].x * 0.125f + mb0;
            sacc[ni].y = sacc[ni].y * 0.125f + mb1;
            sacc[ni].z = sacc[ni].z * 0.125f + mb0;
            sacc[ni].w = sacc[ni].w * 0.125f + mb1;
            rmax0 = fmaxf(rmax0, fmaxf(sacc[ni].x, sacc[ni].y));
            rmax1 = fmaxf(rmax1, fmaxf(sacc[ni].z, sacc[ni].w));
        }
        rmax0 = fmaxf(rmax0, __shfl_xor_sync(0xffffffffu, rmax0, 1));
        rmax0 = fmaxf(rmax0, __shfl_xor_sync(0xffffffffu, rmax0, 2));
        rmax1 = fmaxf(rmax1, __shfl_xor_sync(0xffffffffu, rmax1, 1));
        rmax1 = fmaxf(rmax1, __shfl_xor_sync(0xffffffffu, rmax1, 2));

        const float nm0 = fmaxf(m0, rmax0), nm1 = fmaxf(m1, rmax1);
        const float s0 = (nm0 == NEG_INF) ? 0.f : nm0;
        const float s1 = (nm1 == NEG_INF) ? 0.f : nm1;
        const float f0 = __expf(m0 - s0), f1 = __expf(m1 - s1);
        m0 = nm0; m1 = nm1;

        float rs0 = 0.f, rs1 = 0.f;
#pragma unroll
        for (int ni = 0; ni < 8; ni++) {
            sacc[ni].x = __expf(sacc[ni].x - s0);
            sacc[ni].y = __expf(sacc[ni].y - s0);
            sacc[ni].z = __expf(sacc[ni].z - s1);
            sacc[ni].w = __expf(sacc[ni].w - s1);
            rs0 += sacc[ni].x + sacc[ni].y;
            rs1 += sacc[ni].z + sacc[ni].w;
        }
        rs0 += __shfl_xor_sync(0xffffffffu, rs0, 1);
        rs0 += __shfl_xor_sync(0xffffffffu, rs0, 2);
        rs1 += __shfl_xor_sync(0xffffffffu, rs1, 1);
        rs1 += __shfl_xor_sync(0xffffffffu, rs1, 2);
        l0 = l0 * f0 + rs0;
        l1 = l1 * f1 + rs1;
#pragma unroll
        for (int d = 0; d < 8; d++) {
            oacc[d].x *= f0; oacc[d].y *= f0;
            oacc[d].z *= f1; oacc[d].w *= f1;
        }

        // ---- O += P @ V : C-layout pairs pack directly into A-frags ----
#pragma unroll
        for (int g = 0; g < 4; g++) {
            uint32_t pah[4], pal[4];
            splitpack(sacc[2 * g].x,     sacc[2 * g].y,     pah[0], pal[0]);
            splitpack(sacc[2 * g].z,     sacc[2 * g].w,     pah[1], pal[1]);
            splitpack(sacc[2 * g + 1].x, sacc[2 * g + 1].y, pah[2], pal[2]);
            splitpack(sacc[2 * g + 1].z, sacc[2 * g + 1].w, pah[3], pal[3]);
#pragma unroll
            for (int dc = 0; dc < 8; dc++) {
                const int col = dc * 8 + lg;
                const uint2 V0 = Vs2[col * VSTR + g * 8 + lt];
                const uint2 V1 = Vs2[col * VSTR + g * 8 + 4 + lt];
                mma16(oacc[dc], pah, V0.x, V1.x);
                mma16(oacc[dc], pah, V0.y, V1.y);
                mma16(oacc[dc], pal, V0.x, V1.x);
            }
        }
    }

    // ---- finalize ----
    const float inv0 = 1.f / l0, inv1 = 1.f / l1;
    if (!self_mode) {
        const int r0 = q_start + q0 + wid * 16 + lg;
#pragma unroll
        for (int d = 0; d < 8; d++) {
            const int col = h * HD + d * 8 + lt * 2;
            float2 a = {oacc[d].x * inv0, oacc[d].y * inv0};
            float2 c = {oacc[d].z * inv1, oacc[d].w * inv1};
            *(float2*)(g_attn + (rowbase + r0) * DD + col) = a;
            *(float2*)(g_attn + (rowbase + r0 + 8) * DD + col) = c;
        }
    } else {
        const int p0 = q0 + wid * 16 + lg, p1 = p0 + 8;
#pragma unroll
        for (int d = 0; d < 8; d++) {
            const int k = d * 8 + lt * 2;
#pragma unroll
            for (int e = 0; e < 4; e++) {
                const int kk = k + (e & 1);
                const int pp = (e < 2) ? p0 : p1;
                const float val = ((e == 0) ? oacc[d].x * inv0 :
                                   (e == 1) ? oacc[d].y * inv0 :
                                   (e == 2) ? oacc[d].z * inv1 : oacc[d].w * inv1);
                const int f = (h * HD + kk) * PP + pp;
                g_attn[(rowbase + f / DD) * DD + (f % DD)] = val;
            }
        }
    }
}

// ---------------------------------------------------------------------------
extern "C" void kernel_launch(void* const* d_in, const int* in_sizes, int n_in,
                              void* d_out, int out_size)
{
    const float*    xs     = (const float*)d_in[0];
    const float*    xq     = (const float*)d_in[1];
    const uint32_t* mask   = (const uint32_t*)d_in[2];
    const float*    qkv_w  = (const float*)d_in[3];
    const float*    qkv_b  = (const float*)d_in[4];
    const float*    proj_w = (const float*)d_in[5];
    const float*    proj_b = (const float*)d_in[6];
    float*          out    = (float*)d_out;
    (void)in_sizes; (void)n_in; (void)out_size;

    cudaFuncSetAttribute(gemm_bf<0>, cudaFuncAttributeMaxDynamicSharedMemorySize, GEMM_SMEM);
    cudaFuncSetAttribute(gemm_bf<1>, cudaFuncAttributeMaxDynamicSharedMemorySize, GEMM_SMEM);
    cudaFuncSetAttribute(attn_bf, cudaFuncAttributeMaxDynamicSharedMemorySize, ATTN_SMEM);

    // 0) mask + operand packing
    mask_convert<<<5, 1024>>>(mask);
    pack_act<<<(MTOT * 192) / 256, 256>>>(xs, xq);
    tpack<<<dim3(QKV3 / 32, DD / 32), 256>>>(qkv_w, g_wqkvp, QKV3);
    tpack<<<dim3(DD / 32, DD / 32), 256>>>(proj_w, g_wprojp, DD);

    // 1) QKV projection (3-term bf16)
    gemm_bf<0><<<dim3(QKV3 / 128, MTOT / 128), 256, GEMM_SMEM>>>(g_wqkvp, qkv_b, nullptr);

    // 2) cross attention: Q rows [P, P+N), KV rows [0, 2560)
    attn_bf<<<dim3(NN / 128, HH, BSZ), 256, ATTN_SMEM>>>(PP, ROWS, 0);

    // 3) self attention: Q rows [0, P), KV rows [0, P), scrambled scatter
    attn_bf<<<dim3(PP / 128, HH, BSZ), 256, ATTN_SMEM>>>(0, PP, 1);

    // 4) pack attention output, then proj (3-term bf16) + tuple scatter
    pack_attn<<<(MTOT * 192) / 256, 256>>>();
    gemm_bf<1><<<dim3(DD / 128, MTOT / 128), 256, GEMM_SMEM>>>(g_wprojp, proj_b, out);
}

// round 13
// speedup vs baseline: 1.0059x; 1.0019x over previous
#include <cuda_runtime.h>
#include <cstdint>
#include <cmath>

#define BSZ 2
#define PP 512
#define NN 2048
#define DD 768
#define HH 12
#define HD 64
#define ROWS 2560
#define MTOT 5120
#define QKV3 2304

#define NEG_INF __int_as_float(0xff800000)

// Scratch (__device__ globals: allocation-free rule)
__device__ float g_qkv [(size_t)MTOT * QKV3];     // qkv activations f32
__device__ float g_attn[(size_t)MTOT * DD];       // attention output f32
__device__ uint2 g_actp [(size_t)MTOT * (DD/2)];  // packed bf16 hi/lo pairs, row-major (A operand)
__device__ uint2 g_wqkvp[(size_t)QKV3 * (DD/2)];  // qkv_w transposed+packed [n][k-pairs]
__device__ uint2 g_wprojp[(size_t)DD * (DD/2)];   // proj_w transposed+packed
__device__ float g_mbias[BSZ * ROWS];             // -inf where masked, 0 (padded to 2560)

// ---------------------------------------------------------------------------
// helpers
// ---------------------------------------------------------------------------
__device__ __forceinline__ uint32_t pack2bf(float lo, float hi) {
    uint32_t r;
    asm("cvt.rn.bf16x2.f32 %0, %1, %2;" : "=r"(r) : "f"(hi), "f"(lo));
    return r;
}
// split (x0,x1) -> packed hi pair + packed lo pair
__device__ __forceinline__ void splitpack(float x0, float x1, uint32_t& h, uint32_t& l) {
    h = pack2bf(x0, x1);
    const float h0 = __uint_as_float(h << 16);
    const float h1 = __uint_as_float(h & 0xffff0000u);
    l = pack2bf(x0 - h0, x1 - h1);
}
__device__ __forceinline__ void mma16(float4& d, const uint32_t* a, uint32_t b0, uint32_t b1) {
    asm volatile(
        "mma.sync.aligned.m16n8k16.row.col.f32.bf16.bf16.f32 "
        "{%0,%1,%2,%3},{%4,%5,%6,%7},{%8,%9},{%0,%1,%2,%3};"
        : "+f"(d.x), "+f"(d.y), "+f"(d.z), "+f"(d.w)
        : "r"(a[0]), "r"(a[1]), "r"(a[2]), "r"(a[3]), "r"(b0), "r"(b1));
}

// ---------------------------------------------------------------------------
// Mask: detect dtype (bool8 / int32 / float32), build -inf/0 bias padded to 2560
// ---------------------------------------------------------------------------
__global__ void mask_convert(const uint32_t* __restrict__ mw)
{
    __shared__ int is_bool;
    const int tid = threadIdx.x;
    if (tid == 0) is_bool = 0;
    __syncthreads();
    if (tid < 256) {
        uint32_t w = mw[tid];
        if (w > 1u && w != 0x3F800000u) atomicOr(&is_bool, 1);
    }
    __syncthreads();
    const int i = blockIdx.x * 1024 + tid;
    const int b = i / ROWS, p = i % ROWS;
    float v = 0.0f;
    if (p < PP) {
        const int mi = b * PP + p;
        bool m = is_bool ? (((const uint8_t*)mw)[mi] != 0) : (mw[mi] != 0u);
        v = m ? NEG_INF : 0.0f;
    }
    g_mbias[i] = v;
}

// ---------------------------------------------------------------------------
// Pack activations (virtual concat [xq; xs]) -> g_actp (row-major bf16 hi/lo pairs)
// ---------------------------------------------------------------------------
__global__ void pack_act(const float* __restrict__ xs, const float* __restrict__ xq)
{
    const int i = blockIdx.x * 256 + threadIdx.x;   // over MTOT*192 uint4 entries
    const int row = i / 192, q = i % 192;
    const int b = row / ROWS, r = row % ROWS;
    const float* src = (r < NN) ? xq + ((size_t)b * NN + r) * DD
                                : xs + ((size_t)b * PP + (r - NN)) * DD;
    float4 v = *(const float4*)(src + q * 4);
    uint4 o;
    splitpack(v.x, v.y, o.x, o.y);
    splitpack(v.z, v.w, o.z, o.w);
    ((uint4*)g_actp)[(size_t)row * 192 + q] = o;
}

__global__ void pack_attn()
{
    const int i = blockIdx.x * 256 + threadIdx.x;
    float4 v = *(const float4*)(g_attn + (size_t)i * 4);
    uint4 o;
    splitpack(v.x, v.y, o.x, o.y);
    splitpack(v.z, v.w, o.z, o.w);
    ((uint4*)g_actp)[i] = o;
}

// ---------------------------------------------------------------------------
// Transpose + pack weights: src row-major [768][NB] -> dst [NB][384] uint2
// (k-major pairs per output column), 32x32 smem tiles.
// ---------------------------------------------------------------------------
__global__ void tpack(const float* __restrict__ src, uint2* __restrict__ dst, int NB)
{
    __shared__ float t[32][33];
    const int tid = threadIdx.x;
    const int n0 = blockIdx.x * 32, k0 = blockIdx.y * 32;
#pragma unroll
    for (int s = 0; s < 4; s++) {
        const int r = (tid >> 5) + s * 8, c = tid & 31;
        t[r][c] = src[(size_t)(k0 + r) * NB + n0 + c];
    }
    __syncthreads();
#pragma unroll
    for (int s = 0; s < 2; s++) {
        const int i = (tid >> 4) + s * 16, j = tid & 15;
        uint32_t h, l;
        splitpack(t[2 * j][i], t[2 * j + 1][i], h, l);
        dst[(size_t)(n0 + i) * 384 + k0 / 2 + j] = make_uint2(h, l);
    }
}

// ---------------------------------------------------------------------------
// 3-term bf16 GEMM: C[M x NB] = A[M x 768] @ B[768 x NB] + bias
// A = g_actp (row-major pairs), B = transposed/packed weights.
// 128x128 tile, BK=32, 8 warps (4x2), warp tile 32x64, m16n8k16.
// smem: uint2 arrays, stride 18 (uint4-aligned staging writes).
// EPI 0 -> g_qkv; EPI 1 -> tuple-scatter to output.
// ---------------------------------------------------------------------------
#define GST 18
#define GEMM_SMEM (2 * 128 * GST * 8)

template <int EPI>
__global__ __launch_bounds__(256) void gemm_bf(
    const uint2* __restrict__ Bg, const float* __restrict__ bias, float* __restrict__ Cout)
{
    constexpr int NB = (EPI == 0) ? QKV3 : DD;
    extern __shared__ uint2 sm2[];
    uint2* As2 = sm2;                 // [128][GST]
    uint2* Bs2 = sm2 + 128 * GST;     // [128][GST]

    const int tid = threadIdx.x;
    const int bx = blockIdx.x, by = blockIdx.y;
    const int wid = tid >> 5, lane = tid & 31;
    const int wm = wid >> 1, wn = wid & 1;
    const int lg = lane >> 2, lt = lane & 3;
    const int row0 = by * 128, col0 = bx * 128;

    float4 acc[2][8];
#pragma unroll
    for (int mi = 0; mi < 2; mi++)
#pragma unroll
        for (int ni = 0; ni < 8; ni++) acc[mi][ni] = make_float4(0.f, 0.f, 0.f, 0.f);

    const uint4* Ag4 = (const uint4*)g_actp;
    const uint4* Bg4 = (const uint4*)Bg;
    uint4* As4 = (uint4*)As2;
    uint4* Bs4 = (uint4*)Bs2;

    for (int k0 = 0; k0 < DD; k0 += 32) {
        __syncthreads();
        const int kt = k0 / 4;                     // uint4 offset within row
#pragma unroll
        for (int i = 0; i < 4; i++) {
            const int id = tid + i * 256;          // 1024 entries
            const int r = id >> 3, q = id & 7;
            As4[r * (GST / 2) + q] = Ag4[(size_t)(row0 + r) * 192 + kt + q];
            Bs4[r * (GST / 2) + q] = Bg4[(size_t)(col0 + r) * 192 + kt + q];
        }
        __syncthreads();

#pragma unroll
        for (int ks = 0; ks < 2; ks++) {
            const int kb = ks * 8 + lt;
            uint32_t ah[2][4], al[2][4];
#pragma unroll
            for (int mi = 0; mi < 2; mi++) {
                const int rb = wm * 32 + mi * 16;
                const uint2 A0 = As2[(rb + lg) * GST + kb];
                const uint2 A1 = As2[(rb + 8 + lg) * GST + kb];
                const uint2 A2 = As2[(rb + lg) * GST + kb + 4];
                const uint2 A3 = As2[(rb + 8 + lg) * GST + kb + 4];
                ah[mi][0] = A0.x; ah[mi][1] = A1.x; ah[mi][2] = A2.x; ah[mi][3] = A3.x;
                al[mi][0] = A0.y; al[mi][1] = A1.y; al[mi][2] = A2.y; al[mi][3] = A3.y;
            }
#pragma unroll
            for (int ni = 0; ni < 8; ni++) {
                const int col = wn * 64 + ni * 8 + lg;
                const uint2 B0 = Bs2[col * GST + kb];
                const uint2 B1 = Bs2[col * GST + kb + 4];
#pragma unroll
                for (int mi = 0; mi < 2; mi++) {
                    mma16(acc[mi][ni], ah[mi], B0.x, B1.x);   // hh
                    mma16(acc[mi][ni], ah[mi], B0.y, B1.y);   // hl
                    mma16(acc[mi][ni], al[mi], B0.x, B1.x);   // lh
                }
            }
        }
    }

    // Epilogue
#pragma unroll
    for (int mi = 0; mi < 2; mi++) {
        const int r0 = row0 + wm * 32 + mi * 16 + lg;
#pragma unroll
        for (int ni = 0; ni < 8; ni++) {
            const int col = col0 + wn * 64 + ni * 8 + lt * 2;
            const float b0 = __ldg(&bias[col]), b1 = __ldg(&bias[col + 1]);
            float2 v0 = {acc[mi][ni].x + b0, acc[mi][ni].y + b1};
            float2 v1 = {acc[mi][ni].z + b0, acc[mi][ni].w + b1};
            if (EPI == 0) {
                *(float2*)(g_qkv + (size_t)r0 * NB + col) = v0;
                *(float2*)(g_qkv + (size_t)(r0 + 8) * NB + col) = v1;
            } else {
#pragma unroll
                for (int rr = 0; rr < 2; rr++) {
                    const int g = r0 + rr * 8;
                    const int b = g / ROWS, r = g % ROWS;
                    float* dst = (r < PP)
                        ? Cout + ((size_t)b * PP + r) * DD
                        : Cout + (size_t)BSZ * PP * DD + ((size_t)b * NN + (r - PP)) * DD;
                    *(float2*)(dst + col) = rr ? v1 : v0;
                }
            }
        }
    }
}

// ---------------------------------------------------------------------------
// bf16 3-term flash attention. BQ=128 (8 warps x 16 rows), BKV=64, d=64.
// Q fragments (hi+lo) in registers for the whole KV loop.
// K in smem k-major pairs [kv][d-pair]; V transposed [d][kv-pair].
// P C-layout -> bf16 A-frag via direct pair packing (no shuffles).
// ---------------------------------------------------------------------------
#define QST 34                        // Q/K smem stride (uint2)
#define VSTR 33                       // V smem stride (uint2)
#define ATTN_SMEM (128 * QST * 8 + 512)

__global__ __launch_bounds__(256) void attn_bf(int q_start, int Lk, int self_mode)
{
    extern __shared__ uint2 sm2[];
    uint2* Qs2 = sm2;                            // [128][QST] (staging, then free)
    uint2* Ks2 = sm2;                            // [64][QST]
    uint2* Vs2 = sm2 + 64 * QST;                 // [64][VSTR]
    float* msk = (float*)(sm2 + 64 * QST + 64 * VSTR);   // [64]

    const int tid = threadIdx.x, wid = tid >> 5, lane = tid & 31;
    const int lg = lane >> 2, lt = lane & 3;
    const int h = blockIdx.y, b = blockIdx.z;
    const int q0 = blockIdx.x * 128;
    const size_t rowbase = (size_t)b * ROWS;

    // ---- Stage Q (split+pack) and pull fragments to registers ----
    const float* qg = g_qkv + (rowbase + q_start + q0) * QKV3 + h * HD;
    uint4* Qs4 = (uint4*)Qs2;
#pragma unroll
    for (int i = 0; i < 8; i++) {
        const int id = tid + i * 256;            // 2048 = 128 rows x 16 float4
        const int r = id >> 4, fq = id & 15;
        float4 v = *(const float4*)(qg + (size_t)r * QKV3 + fq * 4);
        uint4 o;
        splitpack(v.x, v.y, o.x, o.y);
        splitpack(v.z, v.w, o.z, o.w);
        Qs4[r * (QST / 2) + fq] = o;
    }
    __syncthreads();
    uint32_t qfh[4][4], qfl[4][4];
    {
        const int qrow = wid * 16 + lg;
#pragma unroll
        for (int kf = 0; kf < 4; kf++) {
            const int kb = kf * 8 + lt;
            const uint2 Q0 = Qs2[qrow * QST + kb];
            const uint2 Q1 = Qs2[(qrow + 8) * QST + kb];
            const uint2 Q2 = Qs2[qrow * QST + kb + 4];
            const uint2 Q3 = Qs2[(qrow + 8) * QST + kb + 4];
            qfh[kf][0] = Q0.x; qfh[kf][1] = Q1.x; qfh[kf][2] = Q2.x; qfh[kf][3] = Q3.x;
            qfl[kf][0] = Q0.y; qfl[kf][1] = Q1.y; qfl[kf][2] = Q2.y; qfl[kf][3] = Q3.y;
        }
    }

    float4 oacc[8];
#pragma unroll
    for (int d = 0; d < 8; d++) oacc[d] = make_float4(0.f, 0.f, 0.f, 0.f);
    float m0 = NEG_INF, m1 = NEG_INF, l0 = 0.f, l1 = 0.f;

    for (int kv0 = 0; kv0 < Lk; kv0 += 64) {
        __syncthreads();
        const float* kg = g_qkv + (rowbase + kv0) * QKV3 + DD + h * HD;
        const float* vg = kg + DD;
        uint4* Ks4 = (uint4*)Ks2;
#pragma unroll
        for (int i = 0; i < 4; i++) {
            const int id = tid + i * 256;        // 1024 = 64 rows x 16 float4
            const int r = id >> 4, fq = id & 15;
            float4 v = *(const float4*)(kg + (size_t)r * QKV3 + fq * 4);
            uint4 o;
            splitpack(v.x, v.y, o.x, o.y);
            splitpack(v.z, v.w, o.z, o.w);
            Ks4[r * (QST / 2) + fq] = o;
        }
        // V transposed: Vs2[d][kvp] = pair over kv
#pragma unroll
        for (int e = 0; e < 8; e++) {
            const int idx = tid + e * 256;       // 2048 = 64 d x 32 kv-pairs
            const int d = idx & 63, kvp = idx >> 6;
            const float f0 = vg[(size_t)(2 * kvp) * QKV3 + d];
            const float f1 = vg[(size_t)(2 * kvp + 1) * QKV3 + d];
            uint32_t hh, ll;
            splitpack(f0, f1, hh, ll);
            Vs2[d * VSTR + kvp] = make_uint2(hh, ll);
        }
        if (tid < 64) msk[tid] = g_mbias[b * ROWS + kv0 + tid];
        __syncthreads();

        // ---- S = Q @ K^T (3-term bf16) ----
        float4 sacc[8];
#pragma unroll
        for (int ni = 0; ni < 8; ni++) sacc[ni] = make_float4(0.f, 0.f, 0.f, 0.f);
#pragma unroll
        for (int kf = 0; kf < 4; kf++) {
            const int kb = kf * 8 + lt;
#pragma unroll
            for (int ni = 0; ni < 8; ni++) {
                const int n = ni * 8 + lg;
                const uint2 K0 = Ks2[n * QST + kb];
                const uint2 K1 = Ks2[n * QST + kb + 4];
                mma16(sacc[ni], qfh[kf], K0.x, K1.x);
                mma16(sacc[ni], qfh[kf], K0.y, K1.y);
                mma16(sacc[ni], qfl[kf], K0.x, K1.x);
            }
        }

        // ---- scale + mask bias, online softmax ----
        float rmax0 = NEG_INF, rmax1 = NEG_INF;
#pragma unroll
        for (int ni = 0; ni < 8; ni++) {
            const float mb0 = msk[ni * 8 + lt * 2];
            const float mb1 = msk[ni * 8 + lt * 2 + 1];
            sacc[ni].x = sacc[ni].x * 0.125f + mb0;
            sacc[ni].y = sacc[ni].y * 0.125f + mb1;
            sacc[ni].z = sacc[ni].z * 0.125f + mb0;
            sacc[ni].w = sacc[ni].w * 0.125f + mb1;
            rmax0 = fmaxf(rmax0, fmaxf(sacc[ni].x, sacc[ni].y));
            rmax1 = fmaxf(rmax1, fmaxf(sacc[ni].z, sacc[ni].w));
        }
        rmax0 = fmaxf(rmax0, __shfl_xor_sync(0xffffffffu, rmax0, 1));
        rmax0 = fmaxf(rmax0, __shfl_xor_sync(0xffffffffu, rmax0, 2));
        rmax1 = fmaxf(rmax1, __shfl_xor_sync(0xffffffffu, rmax1, 1));
        rmax1 = fmaxf(rmax1, __shfl_xor_sync(0xffffffffu, rmax1, 2));

        const float nm0 = fmaxf(m0, rmax0), nm1 = fmaxf(m1, rmax1);
        const float s0 = (nm0 == NEG_INF) ? 0.f : nm0;
        const float s1 = (nm1 == NEG_INF) ? 0.f : nm1;
        const float f0 = __expf(m0 - s0), f1 = __expf(m1 - s1);
        m0 = nm0; m1 = nm1;

        float rs0 = 0.f, rs1 = 0.f;
#pragma unroll
        for (int ni = 0; ni < 8; ni++) {
            sacc[ni].x = __expf(sacc[ni].x - s0);
            sacc[ni].y = __expf(sacc[ni].y - s0);
            sacc[ni].z = __expf(sacc[ni].z - s1);
            sacc[ni].w = __expf(sacc[ni].w - s1);
            rs0 += sacc[ni].x + sacc[ni].y;
            rs1 += sacc[ni].z + sacc[ni].w;
        }
        rs0 += __shfl_xor_sync(0xffffffffu, rs0, 1);
        rs0 += __shfl_xor_sync(0xffffffffu, rs0, 2);
        rs1 += __shfl_xor_sync(0xffffffffu, rs1, 1);
        rs1 += __shfl_xor_sync(0xffffffffu, rs1, 2);
        l0 = l0 * f0 + rs0;
        l1 = l1 * f1 + rs1;
#pragma unroll
        for (int d = 0; d < 8; d++) {
            oacc[d].x *= f0; oacc[d].y *= f0;
            oacc[d].z *= f1; oacc[d].w *= f1;
        }

        // ---- O += P @ V : C-layout pairs pack directly into A-frags ----
#pragma unroll
        for (int g = 0; g < 4; g++) {
            uint32_t pah[4], pal[4];
            splitpack(sacc[2 * g].x,     sacc[2 * g].y,     pah[0], pal[0]);
            splitpack(sacc[2 * g].z,     sacc[2 * g].w,     pah[1], pal[1]);
            splitpack(sacc[2 * g + 1].x, sacc[2 * g + 1].y, pah[2], pal[2]);
            splitpack(sacc[2 * g + 1].z, sacc[2 * g + 1].w, pah[3], pal[3]);
#pragma unroll
            for (int dc = 0; dc < 8; dc++) {
                const int col = dc * 8 + lg;
                const uint2 V0 = Vs2[col * VSTR + g * 8 + lt];
                const uint2 V1 = Vs2[col * VSTR + g * 8 + 4 + lt];
                mma16(oacc[dc], pah, V0.x, V1.x);
                mma16(oacc[dc], pah, V0.y, V1.y);
                mma16(oacc[dc], pal, V0.x, V1.x);
            }
        }
    }

    // ---- finalize ----
    const float inv0 = 1.f / l0, inv1 = 1.f / l1;
    if (!self_mode) {
        const int r0 = q_start + q0 + wid * 16 + lg;
#pragma unroll
        for (int d = 0; d < 8; d++) {
            const int col = h * HD + d * 8 + lt * 2;
            float2 a = {oacc[d].x * inv0, oacc[d].y * inv0};
            float2 c = {oacc[d].z * inv1, oacc[d].w * inv1};
            *(float2*)(g_attn + (rowbase + r0) * DD + col) = a;
            *(float2*)(g_attn + (rowbase + r0 + 8) * DD + col) = c;
        }
    } else {
        const int p0 = q0 + wid * 16 + lg, p1 = p0 + 8;
#pragma unroll
        for (int d = 0; d < 8; d++) {
            const int k = d * 8 + lt * 2;
#pragma unroll
            for (int e = 0; e < 4; e++) {
                const int kk = k + (e & 1);
                const int pp = (e < 2) ? p0 : p1;
                const float val = ((e == 0) ? oacc[d].x * inv0 :
                                   (e == 1) ? oacc[d].y * inv0 :
                                   (e == 2) ? oacc[d].z * inv1 : oacc[d].w * inv1);
                const int f = (h * HD + kk) * PP + pp;
                g_attn[(rowbase + f / DD) * DD + (f % DD)] = val;
            }
        }
    }
}

// ---------------------------------------------------------------------------
extern "C" void kernel_launch(void* const* d_in, const int* in_sizes, int n_in,
                              void* d_out, int out_size)
{
    const float*    xs     = (const float*)d_in[0];
    const float*    xq     = (const float*)d_in[1];
    const uint32_t* mask   = (const uint32_t*)d_in[2];
    const float*    qkv_w  = (const float*)d_in[3];
    const float*    qkv_b  = (const float*)d_in[4];
    const float*    proj_w = (const float*)d_in[5];
    const float*    proj_b = (const float*)d_in[6];
    float*          out    = (float*)d_out;
    (void)in_sizes; (void)n_in; (void)out_size;

    cudaFuncSetAttribute(gemm_bf<0>, cudaFuncAttributeMaxDynamicSharedMemorySize, GEMM_SMEM);
    cudaFuncSetAttribute(gemm_bf<1>, cudaFuncAttributeMaxDynamicSharedMemorySize, GEMM_SMEM);
    cudaFuncSetAttribute(attn_bf, cudaFuncAttributeMaxDynamicSharedMemorySize, ATTN_SMEM);

    // 0) mask + operand packing
    mask_convert<<<5, 1024>>>(mask);
    pack_act<<<(MTOT * 192) / 256, 256>>>(xs, xq);
    tpack<<<dim3(QKV3 / 32, DD / 32), 256>>>(qkv_w, g_wqkvp, QKV3);
    tpack<<<dim3(DD / 32, DD / 32), 256>>>(proj_w, g_wprojp, DD);

    // 1) QKV projection (3-term bf16)
    gemm_bf<0><<<dim3(QKV3 / 128, MTOT / 128), 256, GEMM_SMEM>>>(g_wqkvp, qkv_b, nullptr);

    // 2) cross attention: Q rows [P, P+N), KV rows [0, 2560)
    attn_bf<<<dim3(NN / 128, HH, BSZ), 256, ATTN_SMEM>>>(PP, ROWS, 0);

    // 3) self attention: Q rows [0, P), KV rows [0, P), scrambled scatter
    attn_bf<<<dim3(PP / 128, HH, BSZ), 256, ATTN_SMEM>>>(0, PP, 1);

    // 4) pack attention output, then proj (3-term bf16) + tuple scatter
    pack_attn<<<(MTOT * 192) / 256, 256>>>();
    gemm_bf<1><<<dim3(DD / 128, MTOT / 128), 256, GEMM_SMEM>>>(g_wprojp, proj_b, out);
}